// round 7
// baseline (speedup 1.0000x reference)
#include <cuda_runtime.h>
#include <cstdint>

// Leaky RNN: x_t = 0.9*x_{t-1} + 0.1*(u@Win + tanh(x_{t-1})@Wrec + brec) + q_t
//            z_t = tanh(x_t)@Wout + bout
// T=1024, B=64, NIN=32, N=256, NOUT=16.
//
// Pre : g[t,b,n] = noise + 0.1*(u@Win + brec)  (device scratch)
// A   : 64 CTAs (1/batch), 256 thr. warp w owns k-slice [32w,32w+32);
//       thread (w,l) owns cols {l+32j, j<8}; ALL 256 weights in regs (128 f32x2).
//       Per step: warp broadcasts ONLY its 32-float r-slice (8 LDS.128),
//       128 FFMA2 -> 8 partials -> padded smem reduction -> epilogue col=tid.
// B   : outputs = tanh(states) @ Wout + bout (prefetch-pipelined).

#define T_STEPS 1024
#define B_SZ    64
#define N_IN    32
#define N_HID   256
#define N_OUT   16

typedef unsigned long long ull;

__device__ float g_buf[T_STEPS * B_SZ * N_HID];

__device__ __forceinline__ void ffma2(ull& acc, ull a, ull b) {
    asm("fma.rn.f32x2 %0, %1, %2, %0;" : "+l"(acc) : "l"(a), "l"(b));
}
__device__ __forceinline__ ull pack2(float lo, float hi) {
    ull r; asm("mov.b64 %0, {%1, %2};" : "=l"(r) : "f"(lo), "f"(hi)); return r;
}
__device__ __forceinline__ float hadd2(ull a) {
    float lo, hi; asm("mov.b64 {%0, %1}, %2;" : "=f"(lo), "=f"(hi) : "l"(a));
    return lo + hi;
}
__device__ __forceinline__ float ftanh(float x) {
    float e = __expf(2.0f * x);
    return 1.0f - __fdividef(2.0f, e + 1.0f);
}

// ---------------- Pre-kernel: g = noise + 0.1*(u@Win + brec) ----------------
__global__ void __launch_bounds__(256)
uproj_kernel(const float* __restrict__ inputs,   // [T*B, NIN]
             const float* __restrict__ noise,    // [T*B, N]
             const float* __restrict__ Win,      // [NIN, N]
             const float* __restrict__ brec)     // [N]
{
    __shared__ float su[8][N_IN];
    const int tid = threadIdx.x;

    float w_in[N_IN];
#pragma unroll
    for (int i = 0; i < N_IN; ++i) w_in[i] = Win[i * N_HID + tid];
    const float br = brec[tid];

    const int row0 = blockIdx.x * 8;
    su[tid >> 5][tid & 31] = inputs[row0 * N_IN + tid];
    __syncthreads();

#pragma unroll
    for (int rr = 0; rr < 8; ++rr) {
        const int row = row0 + rr;
        float acc = br;
#pragma unroll
        for (int i = 0; i < N_IN; ++i) acc = fmaf(su[rr][i], w_in[i], acc);
        g_buf[row * N_HID + tid] = noise[row * N_HID + tid] + 0.1f * acc;
    }
}

// ---------------- Kernel A: the recurrence ----------------
#define RED_PAD 264        // 256 + 8 pad: conflict-free STS/LDS

__global__ void __launch_bounds__(256, 1)
rnn_step_kernel(const float* __restrict__ x0,     // [B,N]
                const float* __restrict__ Wrec,   // [N,N]
                float* __restrict__ states)       // [T,B,N]
{
    __shared__ __align__(16) float r_s[2][N_HID];        // r double-buffered
    __shared__ __align__(16) float sRed[2][8][RED_PAD];  // partials, double-buffered

    const int tid  = threadIdx.x;
    const int b    = blockIdx.x;
    const int warp = tid >> 5;
    const int l    = tid & 31;

    // ---- register-stationary weights ----
    // W[j*16+i] = (Wrec[32w+2i][l+32j], Wrec[32w+2i+1][l+32j])
    ull W[128];
#pragma unroll
    for (int j = 0; j < 8; ++j) {
        const int c = l + 32 * j;
#pragma unroll
        for (int i = 0; i < 16; ++i) {
            const int k = 32 * warp + 2 * i;
            W[j * 16 + i] = pack2(Wrec[k * N_HID + c], Wrec[(k + 1) * N_HID + c]);
        }
    }

    // ---- state init: epilogue column = tid ----
    float x = x0[b * N_HID + tid];
    r_s[0][tid] = ftanh(x);

    const float* gp = g_buf + b * N_HID + tid;
    float greg = gp[0];
    float* sp = states + b * N_HID + tid;
    __syncthreads();

#pragma unroll 1
    for (int t = 0; t < T_STEPS; ++t) {
        const int p  = t & 1;
        const int nb = p ^ 1;

        const int tq = (t + 1 < T_STEPS) ? (t + 1) : (T_STEPS - 1);
        const float gnext = gp[tq * (B_SZ * N_HID)];   // prefetch under the dot

        // ---- load own 32-float r slice (8 broadcast LDS.128) ----
        const ulonglong2* rp = reinterpret_cast<const ulonglong2*>(&r_s[p][warp << 5]);
        ull r2[16];
#pragma unroll
        for (int q = 0; q < 8; ++q) {
            ulonglong2 v = rp[q];
            r2[2 * q]     = v.x;
            r2[2 * q + 1] = v.y;
        }

        // ---- 8 column-partials over own k-slice: 128 FFMA2, zero extra LDS ----
        ull acc[8];
#pragma unroll
        for (int j = 0; j < 8; ++j) acc[j] = 0;
#pragma unroll
        for (int i = 0; i < 16; ++i) {
#pragma unroll
            for (int j = 0; j < 8; ++j)
                ffma2(acc[j], W[j * 16 + i], r2[i]);
        }

        // ---- store partials: sRed[p][warp][l+32j], conflict-free ----
#pragma unroll
        for (int j = 0; j < 8; ++j)
            sRed[p][warp][l + 32 * j] = hadd2(acc[j]);

        __syncthreads();

        // ---- epilogue: column n = tid, reduce 8 warp-partials ----
        float s = 0.0f;
#pragma unroll
        for (int jj = 0; jj < 8; ++jj) s += sRed[p][jj][tid];

        x = 0.9f * x + 0.1f * s + greg;
        greg = gnext;

        sp[t * (B_SZ * N_HID)] = x;          // fire-and-forget STG
        r_s[nb][tid] = ftanh(x);

        __syncthreads();                     // r_s[nb] ready for t+1
    }
}

// ---------------- Kernel B: z = tanh(states) @ Wout + bout ----------------
__global__ void __launch_bounds__(256, 1)
rnn_out_kernel(const float* __restrict__ states,  // [T*B, N]
               const float* __restrict__ Wout,    // [N, NOUT]
               const float* __restrict__ bout,    // [NOUT]
               float* __restrict__ outputs)       // [T*B, NOUT]
{
    __shared__ __align__(16) float srow[8][N_HID];

    const int tid  = threadIdx.x;
    const int wid  = tid >> 5;
    const int lane = tid & 31;
    const int o    = lane & 15;
    const int h    = lane >> 4;

    ull w[64];
#pragma unroll
    for (int j = 0; j < 64; ++j) {
        int n = h * 128 + 2 * j;
        w[j] = pack2(Wout[n * N_OUT + o], Wout[(n + 1) * N_OUT + o]);
    }
    const float bo = bout[o];

    const int rows = T_STEPS * B_SZ;
    const int warps_total = (gridDim.x * blockDim.x) >> 5;
    int row = (blockIdx.x * blockDim.x + tid) >> 5;
    if (row >= rows) return;

    const float4* src = reinterpret_cast<const float4*>(states + (size_t)row * N_HID);
    float4 v0 = src[lane];
    float4 v1 = src[32 + lane];

    while (true) {
        const int nrow = row + warps_total;
        float4 n0, n1;
        if (nrow < rows) {
            const float4* nsrc = reinterpret_cast<const float4*>(states + (size_t)nrow * N_HID);
            n0 = nsrc[lane];
            n1 = nsrc[32 + lane];
        }

        v0.x = ftanh(v0.x); v0.y = ftanh(v0.y); v0.z = ftanh(v0.z); v0.w = ftanh(v0.w);
        v1.x = ftanh(v1.x); v1.y = ftanh(v1.y); v1.z = ftanh(v1.z); v1.w = ftanh(v1.w);
        float4* dst = reinterpret_cast<float4*>(&srow[wid][0]);
        dst[lane]      = v0;
        dst[32 + lane] = v1;
        __syncwarp();

        const ulonglong2* rp = reinterpret_cast<const ulonglong2*>(&srow[wid][h << 7]);
        ull a0 = 0, a1 = 0;
#pragma unroll
        for (int gq = 0; gq < 32; ++gq) {
            ulonglong2 q = rp[gq];
            ffma2(a0, w[2 * gq + 0], q.x);
            ffma2(a1, w[2 * gq + 1], q.y);
        }
        float zz = hadd2(a0) + hadd2(a1);
        zz += __shfl_xor_sync(0xffffffffu, zz, 16);
        if (h == 0)
            outputs[(size_t)row * N_OUT + o] = zz + bo;
        __syncwarp();

        if (nrow >= rows) break;
        row = nrow; v0 = n0; v1 = n1;
    }
}

extern "C" void kernel_launch(void* const* d_in, const int* in_sizes, int n_in,
                              void* d_out, int out_size) {
    const float* inputs = (const float*)d_in[0];
    const float* noise  = (const float*)d_in[1];
    const float* x0     = (const float*)d_in[2];
    const float* Win    = (const float*)d_in[3];
    const float* Wrec   = (const float*)d_in[4];
    const float* brec   = (const float*)d_in[5];
    const float* Wout   = (const float*)d_in[6];
    const float* bout   = (const float*)d_in[7];

    float* outputs = (float*)d_out;                                  // [T,B,NOUT]
    float* states  = (float*)d_out + (size_t)T_STEPS * B_SZ * N_OUT; // [T,B,N]

    uproj_kernel<<<dim3(T_STEPS * B_SZ / 8), dim3(256)>>>(inputs, noise, Win, brec);
    rnn_step_kernel<<<dim3(B_SZ), dim3(256)>>>(x0, Wrec, states);
    rnn_out_kernel<<<dim3(592), dim3(256)>>>(states, Wout, bout, outputs);
}

// round 8
// speedup vs baseline: 1.6643x; 1.6643x over previous
#include <cuda_runtime.h>
#include <cstdint>

// Leaky RNN: x_t = 0.9*x_{t-1} + 0.1*(u@Win + tanh(x_{t-1})@Wrec + brec) + q_t
//            z_t = tanh(x_t)@Wout + bout
// T=1024, B=64, NIN=32, N=256, NOUT=16.
//
// Pre : g[t,b,n] = noise + 0.1*(u@Win + brec)  (device scratch)
// A   : 128 CTAs = 64 batches x 2 cluster ranks (k-split!).
//       CTA rank rho owns k-rows AND state cols [128rho, 128rho+128).
//       All 256 threads: col n=tid, partial over own 128 k; 64 ull weights in regs.
//       r-slice = own half only (produced locally) -> 32 broadcast LDS.128/thread
//       = 1024 cyc/SM/step delivery (vs 2048 single-CTA). Partial sums for the
//       peer's cols cross via st.shared::cluster + arrive.release / acquire wait.
// B   : outputs = tanh(states) @ Wout + bout.

#define T_STEPS 1024
#define B_SZ    64
#define N_IN    32
#define N_HID   256
#define N_OUT   16

typedef unsigned long long ull;

__device__ float g_buf[T_STEPS * B_SZ * N_HID];

__device__ __forceinline__ void ffma2(ull& acc, ull a, ull b) {
    asm("fma.rn.f32x2 %0, %1, %2, %0;" : "+l"(acc) : "l"(a), "l"(b));
}
__device__ __forceinline__ ull fadd2(ull a, ull b) {
    ull r; asm("add.rn.f32x2 %0, %1, %2;" : "=l"(r) : "l"(a), "l"(b)); return r;
}
__device__ __forceinline__ ull pack2(float lo, float hi) {
    ull r; asm("mov.b64 %0, {%1, %2};" : "=l"(r) : "f"(lo), "f"(hi)); return r;
}
__device__ __forceinline__ float hadd2(ull a) {
    float lo, hi; asm("mov.b64 {%0, %1}, %2;" : "=f"(lo), "=f"(hi) : "l"(a));
    return lo + hi;
}
__device__ __forceinline__ float ftanh(float x) {
    float e = __expf(2.0f * x);
    return 1.0f - __fdividef(2.0f, e + 1.0f);
}
__device__ __forceinline__ unsigned mapa32(unsigned laddr, unsigned peer) {
    unsigned r;
    asm volatile("mapa.shared::cluster.u32 %0, %1, %2;" : "=r"(r) : "r"(laddr), "r"(peer));
    return r;
}
__device__ __forceinline__ void st_remote_f32(unsigned addr, float v) {
    asm volatile("st.shared::cluster.f32 [%0], %1;" :: "r"(addr), "f"(v) : "memory");
}
__device__ __forceinline__ void arrive_remote(unsigned addr) {
    asm volatile("mbarrier.arrive.release.cluster.shared::cluster.b64 _, [%0];"
                 :: "r"(addr) : "memory");
}
__device__ __forceinline__ void mbar_wait_cluster(unsigned addr, unsigned parity) {
    unsigned done;
    do {
        asm volatile(
            "{\n\t.reg .pred P;\n\t"
            "mbarrier.try_wait.parity.acquire.cluster.shared::cta.b64 P, [%1], %2, 0x989680;\n\t"
            "selp.b32 %0, 1, 0, P;\n\t}"
            : "=r"(done) : "r"(addr), "r"(parity) : "memory");
    } while (!done);
}
#define CLUSTER_SYNC() do { \
    asm volatile("barrier.cluster.arrive.aligned;" ::: "memory"); \
    asm volatile("barrier.cluster.wait.aligned;"   ::: "memory"); } while (0)

// ---------------- Pre-kernel: g = noise + 0.1*(u@Win + brec) ----------------
__global__ void __launch_bounds__(256)
uproj_kernel(const float* __restrict__ inputs,   // [T*B, NIN]
             const float* __restrict__ noise,    // [T*B, N]
             const float* __restrict__ Win,      // [NIN, N]
             const float* __restrict__ brec)     // [N]
{
    __shared__ float su[8][N_IN];
    const int tid = threadIdx.x;

    float w_in[N_IN];
#pragma unroll
    for (int i = 0; i < N_IN; ++i) w_in[i] = Win[i * N_HID + tid];
    const float br = brec[tid];

    const int row0 = blockIdx.x * 8;
    su[tid >> 5][tid & 31] = inputs[row0 * N_IN + tid];
    __syncthreads();

#pragma unroll
    for (int rr = 0; rr < 8; ++rr) {
        const int row = row0 + rr;
        float acc = br;
#pragma unroll
        for (int i = 0; i < N_IN; ++i) acc = fmaf(su[rr][i], w_in[i], acc);
        g_buf[row * N_HID + tid] = noise[row * N_HID + tid] + 0.1f * acc;
    }
}

// ---------------- Kernel A: the recurrence (2-way k-split cluster) ----------------
__global__ void __launch_bounds__(256, 1) __cluster_dims__(2, 1, 1)
rnn_step_kernel(const float* __restrict__ x0,     // [B,N]
                const float* __restrict__ Wrec,   // [N,N]
                float* __restrict__ states)       // [T,B,N]
{
    __shared__ __align__(16) float r_s[2][128];   // own-half r, dbl-buffered
    __shared__ __align__(16) float inbox[2][128]; // peer partials for my cols
    __shared__ __align__(8)  ull   mbar[2];

    const int tid = threadIdx.x;
    const int b   = blockIdx.x >> 1;
    const unsigned rho = blockIdx.x & 1u;
    const int n   = tid;                 // global column this thread computes
    const int li  = tid & 127;           // local index within a half
    const bool owner = ((unsigned)(tid >> 7) == rho);  // warp-uniform split
    const int k0  = (int)rho * 128;      // own k-half base

    // register-stationary weights: W[j] = (Wrec[k0+2j][n], Wrec[k0+2j+1][n])
    ull W[64];
#pragma unroll
    for (int j = 0; j < 64; ++j)
        W[j] = pack2(Wrec[(k0 + 2 * j) * N_HID + n],
                     Wrec[(k0 + 2 * j + 1) * N_HID + n]);

    if (tid == 0) {
        asm volatile("mbarrier.init.shared.b64 [%0], %1;"
                     :: "r"((unsigned)__cvta_generic_to_shared(&mbar[0])), "r"(128) : "memory");
        asm volatile("mbarrier.init.shared.b64 [%0], %1;"
                     :: "r"((unsigned)__cvta_generic_to_shared(&mbar[1])), "r"(128) : "memory");
    }

    float x = 0.0f, greg = 0.0f;
    unsigned r_inbox = 0, r_mbar = 0;
    if (owner) {
        x = x0[b * N_HID + n];
        r_s[0][li] = ftanh(x);           // r_{-1}, own half (local only!)
        greg = g_buf[b * N_HID + n];     // g_0
    } else {
        // sender: precompute remote inbox/mbar addresses on the peer CTA
        unsigned l_in = (unsigned)__cvta_generic_to_shared(&inbox[0][li]);
        r_inbox = mapa32(l_in, rho ^ 1u);
        unsigned l_mb = (unsigned)__cvta_generic_to_shared(&mbar[0]);
        r_mbar = mapa32(l_mb, rho ^ 1u);
    }

    __syncthreads();     // r_s[0] + mbar init visible locally
    CLUSTER_SYNC();      // peer mbar init visible before any remote arrive

    const float* gp = g_buf + b * N_HID + n;
    float* sp = states + b * N_HID + n;
    const unsigned mb0 = (unsigned)__cvta_generic_to_shared(&mbar[0]);
    int ph0 = 0, ph1 = 0;

#pragma unroll 1
    for (int t = 0; t < T_STEPS; ++t) {
        const int p  = t & 1;
        const int nb = p ^ 1;

        // ---- partial over own 128 k: 32 broadcast LDS.128 + 64 FFMA2 ----
        const ulonglong2* rp = reinterpret_cast<const ulonglong2*>(&r_s[p][0]);
        ull a0 = 0, a1 = 0, a2 = 0, a3 = 0;
#pragma unroll
        for (int i = 0; i < 16; ++i) {
            ulonglong2 q0 = rp[2 * i];
            ulonglong2 q1 = rp[2 * i + 1];
            ffma2(a0, W[4 * i + 0], q0.x);
            ffma2(a1, W[4 * i + 1], q0.y);
            ffma2(a2, W[4 * i + 2], q1.x);
            ffma2(a3, W[4 * i + 3], q1.y);
        }
        const float part = hadd2(fadd2(fadd2(a0, a1), fadd2(a2, a3)));

        if (owner) {
            const int tq = (t + 1 < T_STEPS) ? (t + 1) : (T_STEPS - 1);
            const float gnext = gp[tq * (B_SZ * N_HID)];   // prefetch g_{t+1}

            // wait for peer's partials for my column
            if (p == 0) { mbar_wait_cluster(mb0, ph0); ph0 ^= 1; }
            else        { mbar_wait_cluster(mb0 + 8, ph1); ph1 ^= 1; }

            const float tot = part + inbox[p][li];
            x = 0.9f * x + 0.1f * tot + greg;
            greg = gnext;
            r_s[nb][li] = ftanh(x);
            sp[t * (B_SZ * N_HID)] = x;                    // fire-and-forget
        } else {
            // ship partial for the peer's column + signal (release orders the store)
            st_remote_f32(r_inbox + (unsigned)(p * 512), part);
            arrive_remote(r_mbar + (unsigned)(p * 8));
        }

        __syncthreads();     // r_s[nb] visible to all 8 warps for step t+1
    }

    CLUSTER_SYNC();          // keep smem alive until all peer traffic has landed
}

// ---------------- Kernel B: z = tanh(states) @ Wout + bout ----------------
__global__ void __launch_bounds__(256, 1)
rnn_out_kernel(const float* __restrict__ states,  // [T*B, N]
               const float* __restrict__ Wout,    // [N, NOUT]
               const float* __restrict__ bout,    // [NOUT]
               float* __restrict__ outputs)       // [T*B, NOUT]
{
    __shared__ __align__(16) float srow[8][N_HID];

    const int tid  = threadIdx.x;
    const int wid  = tid >> 5;
    const int lane = tid & 31;
    const int o    = lane & 15;
    const int h    = lane >> 4;

    ull w[64];
#pragma unroll
    for (int j = 0; j < 64; ++j) {
        int nn = h * 128 + 2 * j;
        w[j] = pack2(Wout[nn * N_OUT + o], Wout[(nn + 1) * N_OUT + o]);
    }
    const float bo = bout[o];

    const int rows = T_STEPS * B_SZ;
    const int warps_total = (gridDim.x * blockDim.x) >> 5;
    int row = (blockIdx.x * blockDim.x + tid) >> 5;
    if (row >= rows) return;

    const float4* src = reinterpret_cast<const float4*>(states + (size_t)row * N_HID);
    float4 v0 = src[lane];
    float4 v1 = src[32 + lane];

    while (true) {
        const int nrow = row + warps_total;
        float4 n0, n1;
        if (nrow < rows) {
            const float4* nsrc = reinterpret_cast<const float4*>(states + (size_t)nrow * N_HID);
            n0 = nsrc[lane];
            n1 = nsrc[32 + lane];
        }

        v0.x = ftanh(v0.x); v0.y = ftanh(v0.y); v0.z = ftanh(v0.z); v0.w = ftanh(v0.w);
        v1.x = ftanh(v1.x); v1.y = ftanh(v1.y); v1.z = ftanh(v1.z); v1.w = ftanh(v1.w);
        float4* dst = reinterpret_cast<float4*>(&srow[wid][0]);
        dst[lane]      = v0;
        dst[32 + lane] = v1;
        __syncwarp();

        const ulonglong2* rp = reinterpret_cast<const ulonglong2*>(&srow[wid][h << 7]);
        ull a0 = 0, a1 = 0;
#pragma unroll
        for (int gq = 0; gq < 32; ++gq) {
            ulonglong2 q = rp[gq];
            ffma2(a0, w[2 * gq + 0], q.x);
            ffma2(a1, w[2 * gq + 1], q.y);
        }
        float zz = hadd2(a0) + hadd2(a1);
        zz += __shfl_xor_sync(0xffffffffu, zz, 16);
        if (h == 0)
            outputs[(size_t)row * N_OUT + o] = zz + bo;
        __syncwarp();

        if (nrow >= rows) break;
        row = nrow; v0 = n0; v1 = n1;
    }
}

extern "C" void kernel_launch(void* const* d_in, const int* in_sizes, int n_in,
                              void* d_out, int out_size) {
    const float* inputs = (const float*)d_in[0];
    const float* noise  = (const float*)d_in[1];
    const float* x0     = (const float*)d_in[2];
    const float* Win    = (const float*)d_in[3];
    const float* Wrec   = (const float*)d_in[4];
    const float* brec   = (const float*)d_in[5];
    const float* Wout   = (const float*)d_in[6];
    const float* bout   = (const float*)d_in[7];

    float* outputs = (float*)d_out;                                  // [T,B,NOUT]
    float* states  = (float*)d_out + (size_t)T_STEPS * B_SZ * N_OUT; // [T,B,N]

    uproj_kernel<<<dim3(T_STEPS * B_SZ / 8), dim3(256)>>>(inputs, noise, Win, brec);
    rnn_step_kernel<<<dim3(B_SZ * 2), dim3(256)>>>(x0, Wrec, states);
    rnn_out_kernel<<<dim3(592), dim3(256)>>>(states, Wout, bout, outputs);
}

// round 9
// speedup vs baseline: 1.8256x; 1.0969x over previous
#include <cuda_runtime.h>
#include <cstdint>

// Leaky RNN: x_t = 0.9*x_{t-1} + 0.1*(u@Win + tanh(x_{t-1})@Wrec + brec) + q_t
//            z_t = tanh(x_t)@Wout + bout
// T=1024, B=64, NIN=32, N=256, NOUT=16.
//
// Pre : g[t,b,n] = noise + 0.1*(u@Win + brec)
// A   : 128 CTAs = 64 batches x 2 cluster ranks (k-split halves).
//       Within CTA: thread (s=tid>>6, c=tid&63) computes 4 cols {c+64j} over
//       k-sub [128*rho+32s, +32). Weights 4x16 packed f32x2 = 128 regs worth? no:
//       64 ull = 128 regs of weights -- fits. r-read = 32 floats/thread
//       -> delivery 256 cyc/step (was 1024). Partials reduced via smem; peer-col
//       sums cross via st.shared::cluster + arrive.release (R8-proven protocol).
// B   : outputs = tanh(states) @ Wout + bout.

#define T_STEPS 1024
#define B_SZ    64
#define N_IN    32
#define N_HID   256
#define N_OUT   16

typedef unsigned long long ull;

__device__ float g_buf[T_STEPS * B_SZ * N_HID];

__device__ __forceinline__ void ffma2(ull& acc, ull a, ull b) {
    asm("fma.rn.f32x2 %0, %1, %2, %0;" : "+l"(acc) : "l"(a), "l"(b));
}
__device__ __forceinline__ ull pack2(float lo, float hi) {
    ull r; asm("mov.b64 %0, {%1, %2};" : "=l"(r) : "f"(lo), "f"(hi)); return r;
}
__device__ __forceinline__ float hadd2(ull a) {
    float lo, hi; asm("mov.b64 {%0, %1}, %2;" : "=f"(lo), "=f"(hi) : "l"(a));
    return lo + hi;
}
__device__ __forceinline__ float ftanh(float x) {
    float e = __expf(2.0f * x);
    return 1.0f - __fdividef(2.0f, e + 1.0f);
}
__device__ __forceinline__ unsigned mapa32(unsigned laddr, unsigned peer) {
    unsigned r;
    asm volatile("mapa.shared::cluster.u32 %0, %1, %2;" : "=r"(r) : "r"(laddr), "r"(peer));
    return r;
}
__device__ __forceinline__ void st_remote_f32(unsigned addr, float v) {
    asm volatile("st.shared::cluster.f32 [%0], %1;" :: "r"(addr), "f"(v) : "memory");
}
__device__ __forceinline__ void arrive_remote(unsigned addr) {
    asm volatile("mbarrier.arrive.release.cluster.shared::cluster.b64 _, [%0];"
                 :: "r"(addr) : "memory");
}
__device__ __forceinline__ void mbar_wait_cluster(unsigned addr, unsigned parity) {
    unsigned done;
    do {
        asm volatile(
            "{\n\t.reg .pred P;\n\t"
            "mbarrier.try_wait.parity.acquire.cluster.shared::cta.b64 P, [%1], %2, 0x989680;\n\t"
            "selp.b32 %0, 1, 0, P;\n\t}"
            : "=r"(done) : "r"(addr), "r"(parity) : "memory");
    } while (!done);
}
#define CLUSTER_SYNC() do { \
    asm volatile("barrier.cluster.arrive.aligned;" ::: "memory"); \
    asm volatile("barrier.cluster.wait.aligned;"   ::: "memory"); } while (0)

// ---------------- Pre-kernel: g = noise + 0.1*(u@Win + brec) ----------------
__global__ void __launch_bounds__(256)
uproj_kernel(const float* __restrict__ inputs,   // [T*B, NIN]
             const float* __restrict__ noise,    // [T*B, N]
             const float* __restrict__ Win,      // [NIN, N]
             const float* __restrict__ brec)     // [N]
{
    __shared__ float su[8][N_IN];
    const int tid = threadIdx.x;

    float w_in[N_IN];
#pragma unroll
    for (int i = 0; i < N_IN; ++i) w_in[i] = Win[i * N_HID + tid];
    const float br = brec[tid];

    const int row0 = blockIdx.x * 8;
    su[tid >> 5][tid & 31] = inputs[row0 * N_IN + tid];
    __syncthreads();

#pragma unroll
    for (int rr = 0; rr < 8; ++rr) {
        const int row = row0 + rr;
        float acc = br;
#pragma unroll
        for (int i = 0; i < N_IN; ++i) acc = fmaf(su[rr][i], w_in[i], acc);
        g_buf[row * N_HID + tid] = noise[row * N_HID + tid] + 0.1f * acc;
    }
}

// ---------------- Kernel A: recurrence, 2-CTA k-split + 4-way sub-slicing ----------------
#define RP 136     // padded partial row (conflict-free, 16B-mult)

__global__ void __launch_bounds__(256, 1) __cluster_dims__(2, 1, 1)
rnn_step_kernel(const float* __restrict__ x0,     // [B,N]
                const float* __restrict__ Wrec,   // [N,N]
                float* __restrict__ states)       // [T,B,N]
{
    __shared__ __align__(16) float r_s[2][128];    // own-half r, dbl-buffered
    __shared__ __align__(16) float sRed[4][RP];    // own-col partials  [s][local col]
    __shared__ __align__(16) float sPeer[4][RP];   // peer-col partials [s][peer-local col]
    __shared__ __align__(16) float inbox[2][128];  // peer's summed partials for my cols
    __shared__ __align__(8)  ull   mbar[2];

    const int tid = threadIdx.x;
    const int b   = blockIdx.x >> 1;
    const unsigned rho = blockIdx.x & 1u;
    const int s   = tid >> 6;            // k sub-slice 0..3
    const int c   = tid & 63;            // column base within group
    const int k0  = (int)rho * 128 + 32 * s;

    // weights: Wj[i] = (Wrec[k0+2i][c+64j], Wrec[k0+2i+1][c+64j]), 64 ull total
    ull W0[16], W1[16], W2[16], W3[16];
#pragma unroll
    for (int i = 0; i < 16; ++i) {
        const int k = k0 + 2 * i;
        W0[i] = pack2(Wrec[k * N_HID + c],       Wrec[(k + 1) * N_HID + c]);
        W1[i] = pack2(Wrec[k * N_HID + c + 64],  Wrec[(k + 1) * N_HID + c + 64]);
        W2[i] = pack2(Wrec[k * N_HID + c + 128], Wrec[(k + 1) * N_HID + c + 128]);
        W3[i] = pack2(Wrec[k * N_HID + c + 192], Wrec[(k + 1) * N_HID + c + 192]);
    }

    if (tid == 0) {
        asm volatile("mbarrier.init.shared.b64 [%0], %1;"
                     :: "r"((unsigned)__cvta_generic_to_shared(&mbar[0])), "r"(128) : "memory");
        asm volatile("mbarrier.init.shared.b64 [%0], %1;"
                     :: "r"((unsigned)__cvta_generic_to_shared(&mbar[1])), "r"(128) : "memory");
    }

    float x = 0.0f, greg = 0.0f;
    unsigned r_inbox = 0, r_mbar = 0;
    const float* gp = g_buf + b * N_HID + (int)rho * 128 + tid;   // owner cols (tid<128)
    float* sp = states + b * N_HID + (int)rho * 128 + tid;

    if (tid < 128) {                      // state owner for local col tid
        x = x0[b * N_HID + (int)rho * 128 + tid];
        r_s[0][tid] = ftanh(x);
        greg = gp[0];
    } else {                              // sender for peer-local col tid-128
        const int li = tid - 128;
        unsigned l_in = (unsigned)__cvta_generic_to_shared(&inbox[0][li]);
        r_inbox = mapa32(l_in, rho ^ 1u);
        unsigned l_mb = (unsigned)__cvta_generic_to_shared(&mbar[0]);
        r_mbar = mapa32(l_mb, rho ^ 1u);
    }

    __syncthreads();
    CLUSTER_SYNC();                       // peer mbar init visible

    const unsigned mb0 = (unsigned)__cvta_generic_to_shared(&mbar[0]);
    int ph0 = 0, ph1 = 0;

#pragma unroll 1
    for (int t = 0; t < T_STEPS; ++t) {
        const int p  = t & 1;
        const int nbuf = p ^ 1;

        // ---- dot: 32-float r sub-slice, 8 LDS.128, 64 FFMA2 ----
        const ulonglong2* rp = reinterpret_cast<const ulonglong2*>(&r_s[p][32 * s]);
        ull a0 = 0, a1 = 0, a2 = 0, a3 = 0;
#pragma unroll
        for (int q = 0; q < 8; ++q) {
            ulonglong2 v = rp[q];
            ffma2(a0, W0[2 * q], v.x);  ffma2(a0, W0[2 * q + 1], v.y);
            ffma2(a1, W1[2 * q], v.x);  ffma2(a1, W1[2 * q + 1], v.y);
            ffma2(a2, W2[2 * q], v.x);  ffma2(a2, W2[2 * q + 1], v.y);
            ffma2(a3, W3[2 * q], v.x);  ffma2(a3, W3[2 * q + 1], v.y);
        }
        const float p0 = hadd2(a0), p1 = hadd2(a1), p2 = hadd2(a2), p3 = hadd2(a3);

        // own cols = [128rho,128rho+128) -> j-offset 2*rho; peer = other two
        if (rho == 0) {
            sRed[s][c]       = p0;  sRed[s][c + 64]  = p1;
            sPeer[s][c]      = p2;  sPeer[s][c + 64] = p3;
        } else {
            sRed[s][c]       = p2;  sRed[s][c + 64]  = p3;
            sPeer[s][c]      = p0;  sPeer[s][c + 64] = p1;
        }

        __syncthreads();    // partials visible

        if (tid < 128) {
            const int tq = (t + 1 < T_STEPS) ? (t + 1) : (T_STEPS - 1);
            const float gnext = gp[tq * (B_SZ * N_HID)];

            float own = (sRed[0][tid] + sRed[1][tid]) + (sRed[2][tid] + sRed[3][tid]);

            if (p == 0) { mbar_wait_cluster(mb0, ph0); ph0 ^= 1; }
            else        { mbar_wait_cluster(mb0 + 8, ph1); ph1 ^= 1; }

            const float tot = own + inbox[p][tid];
            x = 0.9f * x + 0.1f * tot + greg;
            greg = gnext;
            r_s[nbuf][tid] = ftanh(x);
            sp[t * (B_SZ * N_HID)] = x;
        } else {
            const int li = tid - 128;
            const float ps = (sPeer[0][li] + sPeer[1][li]) + (sPeer[2][li] + sPeer[3][li]);
            st_remote_f32(r_inbox + (unsigned)(p * 512), ps);
            arrive_remote(r_mbar + (unsigned)(p * 8));
        }

        __syncthreads();    // r_s[nbuf] ready; sRed/sPeer reusable
    }

    CLUSTER_SYNC();
}

// ---------------- Kernel B: z = tanh(states) @ Wout + bout ----------------
__global__ void __launch_bounds__(256, 1)
rnn_out_kernel(const float* __restrict__ states,  // [T*B, N]
               const float* __restrict__ Wout,    // [N, NOUT]
               const float* __restrict__ bout,    // [NOUT]
               float* __restrict__ outputs)       // [T*B, NOUT]
{
    __shared__ __align__(16) float srow[8][N_HID];

    const int tid  = threadIdx.x;
    const int wid  = tid >> 5;
    const int lane = tid & 31;
    const int o    = lane & 15;
    const int h    = lane >> 4;

    ull w[64];
#pragma unroll
    for (int j = 0; j < 64; ++j) {
        int nn = h * 128 + 2 * j;
        w[j] = pack2(Wout[nn * N_OUT + o], Wout[(nn + 1) * N_OUT + o]);
    }
    const float bo = bout[o];

    const int rows = T_STEPS * B_SZ;
    const int warps_total = (gridDim.x * blockDim.x) >> 5;
    int row = (blockIdx.x * blockDim.x + tid) >> 5;
    if (row >= rows) return;

    const float4* src = reinterpret_cast<const float4*>(states + (size_t)row * N_HID);
    float4 v0 = src[lane];
    float4 v1 = src[32 + lane];

    while (true) {
        const int nrow = row + warps_total;
        float4 n0, n1;
        if (nrow < rows) {
            const float4* nsrc = reinterpret_cast<const float4*>(states + (size_t)nrow * N_HID);
            n0 = nsrc[lane];
            n1 = nsrc[32 + lane];
        }

        v0.x = ftanh(v0.x); v0.y = ftanh(v0.y); v0.z = ftanh(v0.z); v0.w = ftanh(v0.w);
        v1.x = ftanh(v1.x); v1.y = ftanh(v1.y); v1.z = ftanh(v1.z); v1.w = ftanh(v1.w);
        float4* dst = reinterpret_cast<float4*>(&srow[wid][0]);
        dst[lane]      = v0;
        dst[32 + lane] = v1;
        __syncwarp();

        const ulonglong2* rp = reinterpret_cast<const ulonglong2*>(&srow[wid][h << 7]);
        ull a0 = 0, a1 = 0;
#pragma unroll
        for (int gq = 0; gq < 32; ++gq) {
            ulonglong2 q = rp[gq];
            ffma2(a0, w[2 * gq + 0], q.x);
            ffma2(a1, w[2 * gq + 1], q.y);
        }
        float zz = hadd2(a0) + hadd2(a1);
        zz += __shfl_xor_sync(0xffffffffu, zz, 16);
        if (h == 0)
            outputs[(size_t)row * N_OUT + o] = zz + bo;
        __syncwarp();

        if (nrow >= rows) break;
        row = nrow; v0 = n0; v1 = n1;
    }
}

extern "C" void kernel_launch(void* const* d_in, const int* in_sizes, int n_in,
                              void* d_out, int out_size) {
    const float* inputs = (const float*)d_in[0];
    const float* noise  = (const float*)d_in[1];
    const float* x0     = (const float*)d_in[2];
    const float* Win    = (const float*)d_in[3];
    const float* Wrec   = (const float*)d_in[4];
    const float* brec   = (const float*)d_in[5];
    const float* Wout   = (const float*)d_in[6];
    const float* bout   = (const float*)d_in[7];

    float* outputs = (float*)d_out;                                  // [T,B,NOUT]
    float* states  = (float*)d_out + (size_t)T_STEPS * B_SZ * N_OUT; // [T,B,N]

    uproj_kernel<<<dim3(T_STEPS * B_SZ / 8), dim3(256)>>>(inputs, noise, Win, brec);
    rnn_step_kernel<<<dim3(B_SZ * 2), dim3(256)>>>(x0, Wrec, states);
    rnn_out_kernel<<<dim3(592), dim3(256)>>>(states, Wout, bout, outputs);
}